// round 13
// baseline (speedup 1.0000x reference)
#include <cuda_runtime.h>
#include <cstdint>
#include <math.h>

#define D_MODEL 1024
#define NHEAD   16
#define DK      64
#define BATCH   2
#define NQ      2048
#define NKV     2048

// Scratch (allocation-free)
__device__ float g_Q[BATCH * NQ * D_MODEL];
__device__ float g_attn[BATCH * NQ * D_MODEL];

__device__ __forceinline__ float to_tf32(float x) {
    float r; asm("cvt.rna.tf32.f32 %0, %1;" : "=f"(r) : "f"(x));
    return r;
}
__device__ __forceinline__ uint32_t tf32u(float x) {
    return __float_as_uint(to_tf32(x));
}
__device__ __forceinline__ float ex2f(float x) {
    float r; asm("ex2.approx.f32 %0, %1;" : "=f"(r) : "f"(x)); return r;
}

// m16n8k8 tf32 mma (sm_80+ path; compiles for plain sm_103)
__device__ __forceinline__ void mma_tf32(float* c, const uint32_t* a,
                                         uint32_t b0, uint32_t b1) {
    asm volatile(
        "mma.sync.aligned.m16n8k8.row.col.f32.tf32.tf32.f32 "
        "{%0,%1,%2,%3},{%4,%5,%6,%7},{%8,%9},{%0,%1,%2,%3};"
        : "+f"(c[0]), "+f"(c[1]), "+f"(c[2]), "+f"(c[3])
        : "r"(a[0]), "r"(a[1]), "r"(a[2]), "r"(a[3]), "r"(b0), "r"(b1));
}

// ----------------------------------------------------------------------------
// Tensor-core GEMM, tf32x1, single-barrier double-buffered pipeline:
//   LDG(next)->regs ; mma(buf) ; cvt+store->buf^1 ; bar
// 128x128 tile, K-chunk 16, 8 warps 4x2.
// Strides: A 20 (banks 20g+tg), B 136 (banks 8tg+g) -> conflict-free.
// ----------------------------------------------------------------------------
__global__ __launch_bounds__(256, 2) void gemm_tc(const float* __restrict__ A,
                                                  const float* __restrict__ B,
                                                  float* __restrict__ C,
                                                  int M, int N, int K)
{
    __shared__ float Ash[2][128][20];
    __shared__ float Bsh[2][16][136];

    const int tid  = threadIdx.x;
    const int warp = tid >> 5;
    const int lane = tid & 31;
    const int g    = lane >> 2;
    const int tg   = lane & 3;
    const int wm   = (warp & 3) * 32;
    const int wn   = (warp >> 2) * 64;
    const int cRow = blockIdx.y * 128;
    const int cCol = blockIdx.x * 128;

    const int ar  = tid >> 2;         // A rows ar, ar+64
    const int ac4 = (tid & 3) * 4;    // A col group
    const int br  = tid >> 5;         // B rows br, br+8
    const int bc4 = (tid & 31) * 4;   // B col group

    float cacc[2][8][4];
#pragma unroll
    for (int mt = 0; mt < 2; mt++)
#pragma unroll
        for (int nt = 0; nt < 8; nt++)
#pragma unroll
            for (int j = 0; j < 4; j++) cacc[mt][nt][j] = 0.f;

    float4 pa0, pa1, pb0, pb1;
    auto ldg_chunk = [&](int kc) {
        const int k0 = kc * 16;
        pa0 = *(const float4*)&A[(size_t)(cRow + ar) * K + k0 + ac4];
        pa1 = *(const float4*)&A[(size_t)(cRow + ar + 64) * K + k0 + ac4];
        pb0 = *(const float4*)&B[(size_t)(k0 + br) * N + cCol + bc4];
        pb1 = *(const float4*)&B[(size_t)(k0 + br + 8) * N + cCol + bc4];
    };
    auto store_chunk = [&](int buf) {
        float4 hv;
#define CVT4(src, dsth) \
        hv.x = to_tf32(src.x); hv.y = to_tf32(src.y); \
        hv.z = to_tf32(src.z); hv.w = to_tf32(src.w); \
        *(float4*)&dsth = hv;
        CVT4(pa0, Ash[buf][ar][ac4]);
        CVT4(pa1, Ash[buf][ar + 64][ac4]);
        CVT4(pb0, Bsh[buf][br][bc4]);
        CVT4(pb1, Bsh[buf][br + 8][bc4]);
#undef CVT4
    };

    const int NC = K / 16;
    ldg_chunk(0);
    store_chunk(0);
    __syncthreads();

    for (int kc = 0; kc < NC; kc++) {
        const int buf = kc & 1;
        if (kc + 1 < NC) ldg_chunk(kc + 1);   // latency hides under mma below

        // ---- mma over 2 k-steps of 8 ----
#pragma unroll
        for (int ks = 0; ks < 2; ks++) {
            const int k8 = ks * 8;
            uint32_t ah[2][4];
#pragma unroll
            for (int mt = 0; mt < 2; mt++) {
                int m0 = wm + mt * 16 + g;
                ah[mt][0] = __float_as_uint(Ash[buf][m0][k8 + tg]);
                ah[mt][1] = __float_as_uint(Ash[buf][m0 + 8][k8 + tg]);
                ah[mt][2] = __float_as_uint(Ash[buf][m0][k8 + tg + 4]);
                ah[mt][3] = __float_as_uint(Ash[buf][m0 + 8][k8 + tg + 4]);
            }
#pragma unroll
            for (int nt = 0; nt < 8; nt++) {
                int n0 = wn + nt * 8 + g;
                uint32_t bh0 = __float_as_uint(Bsh[buf][k8 + tg][n0]);
                uint32_t bh1 = __float_as_uint(Bsh[buf][k8 + tg + 4][n0]);
#pragma unroll
                for (int mt = 0; mt < 2; mt++)
                    mma_tf32(cacc[mt][nt], ah[mt], bh0, bh1);
            }
        }

        if (kc + 1 < NC) store_chunk(buf ^ 1);   // other warps read buf only
        __syncthreads();
    }

#pragma unroll
    for (int mt = 0; mt < 2; mt++) {
        int row0 = cRow + wm + mt * 16 + g;
#pragma unroll
        for (int nt = 0; nt < 8; nt++) {
            int col = cCol + wn + nt * 8 + 2 * tg;
            *(float2*)&C[(size_t)row0 * N + col]       = make_float2(cacc[mt][nt][0], cacc[mt][nt][1]);
            *(float2*)&C[(size_t)(row0 + 8) * N + col] = make_float2(cacc[mt][nt][2], cacc[mt][nt][3]);
        }
    }
}

// ----------------------------------------------------------------------------
// Tensor-core attention (tf32 mma, exp-without-max), single-barrier
// double-buffered K/V pipeline. K prefetched before QK, V after syncwarp
// (staggers register liveness under the 128-reg cap).
// ----------------------------------------------------------------------------
struct AttnSmem {
    uint32_t Ks[2][64][68];
    uint32_t Vs[2][64][72];
    uint32_t Ps[128][68];
    float    kvsel[2][64];
    float    vred[64];
};

__global__ __launch_bounds__(256, 2) void attn_mma(
    const float* __restrict__ Q,
    const float* __restrict__ Kin,
    const float* __restrict__ Vin,
    const unsigned* __restrict__ kvmask,
    const unsigned* __restrict__ qmask,
    float* __restrict__ attn)
{
    extern __shared__ AttnSmem smem_raw[];
    AttnSmem& s = smem_raw[0];

    const int tid  = threadIdx.x;
    const int warp = tid >> 5;
    const int lane = tid & 31;
    const int g    = lane >> 2;
    const int tg   = lane & 3;
    const int b    = blockIdx.z;
    const int h    = blockIdx.y;
    const int q0   = blockIdx.x * 128;
    const int qb   = warp * 16;
    const float C2 = 0.18033688011112042f;   // 0.125 * log2(e)

    uint32_t qf[8][4];
    {
        const float* qp = Q + (size_t)(b * NQ + q0 + qb) * D_MODEL + h * DK;
#pragma unroll
        for (int ks = 0; ks < 8; ks++) {
            qf[ks][0] = tf32u(qp[(size_t)g       * D_MODEL + 8 * ks + tg]);
            qf[ks][1] = tf32u(qp[(size_t)(g + 8) * D_MODEL + 8 * ks + tg]);
            qf[ks][2] = tf32u(qp[(size_t)g       * D_MODEL + 8 * ks + tg + 4]);
            qf[ks][3] = tf32u(qp[(size_t)(g + 8) * D_MODEL + 8 * ks + tg + 4]);
        }
    }

    float of[8][4];
#pragma unroll
    for (int nt = 0; nt < 8; nt++)
#pragma unroll
        for (int j = 0; j < 4; j++) of[nt][j] = 0.f;
    float l0 = 0.f, l1 = 0.f;
    float4 vsum = make_float4(0.f, 0.f, 0.f, 0.f);

    if (tid < 64) s.vred[tid] = 0.f;

    const float* Kb = Kin + (size_t)(b * NHEAD + h) * NKV * DK;
    const float* Vb = Vin + (size_t)(b * NHEAD + h) * NKV * DK;
    // staging: thread covers rows r0+16i, cols c4..c4+3
    const int c4 = (tid & 15) * 4;
    const int r0 = tid >> 4;

    // ---- stage tile 0 into buf 0 ----
#pragma unroll
    for (int i = 0; i < 4; i++) {
        int r = r0 + i * 16;
        float4 k4 = *(const float4*)&Kb[(size_t)r * DK + c4];
        uint4 ku = make_uint4(tf32u(k4.x), tf32u(k4.y), tf32u(k4.z), tf32u(k4.w));
        *(uint4*)&s.Ks[0][r][c4] = ku;
        float4 v4 = *(const float4*)&Vb[(size_t)r * DK + c4];
        vsum.x += v4.x; vsum.y += v4.y; vsum.z += v4.z; vsum.w += v4.w;
        uint4 vu = make_uint4(tf32u(v4.x), tf32u(v4.y), tf32u(v4.z), tf32u(v4.w));
        *(uint4*)&s.Vs[0][r][c4] = vu;
    }
    if (tid < 64)
        s.kvsel[0][tid] = (kvmask[b * NKV + tid] != 0u) ? 0.f : -1e9f;
    __syncthreads();

    const int NT = NKV / 64;
    for (int t = 0; t < NT; t++) {
        const int buf = t & 1;
        const bool pre = (t + 1 < NT);
        const int k0n = (t + 1) * 64;

        // ---- prefetch K tile t+1 (consumed at store below; hides under QK) ----
        float4 kpre[4];
        unsigned kvm_next = 0u;
        if (pre) {
#pragma unroll
            for (int i = 0; i < 4; i++)
                kpre[i] = *(const float4*)&Kb[(size_t)(k0n + r0 + i * 16) * DK + c4];
            if (tid < 64) kvm_next = kvmask[b * NKV + k0n + tid];
        }

        // ---- S = Q K^T ----
        float sc[8][4];
#pragma unroll
        for (int nt = 0; nt < 8; nt++)
#pragma unroll
            for (int j = 0; j < 4; j++) sc[nt][j] = 0.f;
#pragma unroll
        for (int ks = 0; ks < 8; ks++) {
#pragma unroll
            for (int nt = 0; nt < 8; nt++) {
                uint32_t kb0 = s.Ks[buf][8 * nt + g][8 * ks + tg];
                uint32_t kb1 = s.Ks[buf][8 * nt + g][8 * ks + tg + 4];
                mma_tf32(sc[nt], qf[ks], kb0, kb1);
            }
        }

        // ---- epilogue: p = 2^(s*C2 + sel), accumulate l, store P (tf32) ----
#pragma unroll
        for (int nt = 0; nt < 8; nt++) {
            float s0 = s.kvsel[buf][8 * nt + 2 * tg];
            float s1 = s.kvsel[buf][8 * nt + 2 * tg + 1];
            float p0 = ex2f(fmaf(sc[nt][0], C2, s0));
            float p1 = ex2f(fmaf(sc[nt][1], C2, s1));
            float p2 = ex2f(fmaf(sc[nt][2], C2, s0));
            float p3 = ex2f(fmaf(sc[nt][3], C2, s1));
            l0 += p0 + p1;
            l1 += p2 + p3;
            uint2 w0 = make_uint2(tf32u(p0), tf32u(p1));
            uint2 w1 = make_uint2(tf32u(p2), tf32u(p3));
            *(uint2*)&s.Ps[qb + g][8 * nt + 2 * tg]     = w0;
            *(uint2*)&s.Ps[qb + g + 8][8 * nt + 2 * tg] = w1;
        }
        __syncwarp();   // Ps is warp-private

        // ---- prefetch V tile t+1 (consumed at store below; hides under PV) ----
        float4 vpre[4];
        if (pre) {
#pragma unroll
            for (int i = 0; i < 4; i++)
                vpre[i] = *(const float4*)&Vb[(size_t)(k0n + r0 + i * 16) * DK + c4];
        }

        // ---- O += P V ----
#pragma unroll
        for (int ks = 0; ks < 8; ks++) {
            uint32_t pa[4];
            pa[0] = s.Ps[qb + g][8 * ks + tg];
            pa[1] = s.Ps[qb + g + 8][8 * ks + tg];
            pa[2] = s.Ps[qb + g][8 * ks + tg + 4];
            pa[3] = s.Ps[qb + g + 8][8 * ks + tg + 4];
#pragma unroll
            for (int nt = 0; nt < 8; nt++) {
                uint32_t vb0 = s.Vs[buf][8 * ks + tg][8 * nt + g];
                uint32_t vb1 = s.Vs[buf][8 * ks + tg + 4][8 * nt + g];
                mma_tf32(of[nt], pa, vb0, vb1);
            }
        }

        // ---- store tile t+1 into buf^1 (other warps read buf only) ----
        if (pre) {
#pragma unroll
            for (int i = 0; i < 4; i++) {
                int r = r0 + i * 16;
                uint4 ku = make_uint4(tf32u(kpre[i].x), tf32u(kpre[i].y),
                                      tf32u(kpre[i].z), tf32u(kpre[i].w));
                *(uint4*)&s.Ks[buf ^ 1][r][c4] = ku;
                vsum.x += vpre[i].x; vsum.y += vpre[i].y;
                vsum.z += vpre[i].z; vsum.w += vpre[i].w;
                uint4 vu = make_uint4(tf32u(vpre[i].x), tf32u(vpre[i].y),
                                      tf32u(vpre[i].z), tf32u(vpre[i].w));
                *(uint4*)&s.Vs[buf ^ 1][r][c4] = vu;
            }
            if (tid < 64)
                s.kvsel[buf ^ 1][tid] = kvm_next ? 0.f : -1e9f;
        }
        __syncthreads();
    }

    atomicAdd(&s.vred[c4 + 0], vsum.x);
    atomicAdd(&s.vred[c4 + 1], vsum.y);
    atomicAdd(&s.vred[c4 + 2], vsum.z);
    atomicAdd(&s.vred[c4 + 3], vsum.w);
    __syncthreads();

    l0 += __shfl_xor_sync(0xffffffffu, l0, 1);
    l0 += __shfl_xor_sync(0xffffffffu, l0, 2);
    l1 += __shfl_xor_sync(0xffffffffu, l1, 1);
    l1 += __shfl_xor_sync(0xffffffffu, l1, 2);
    const float inv0 = 1.f / l0;
    const float inv1 = 1.f / l1;
    const bool qok0 = (qmask[b * NQ + q0 + qb + g]     != 0u);
    const bool qok1 = (qmask[b * NQ + q0 + qb + g + 8] != 0u);
    const float u = 1.f / 2048.f;

    float* op0 = attn + (size_t)(b * NQ + q0 + qb + g)     * D_MODEL + h * DK;
    float* op1 = attn + (size_t)(b * NQ + q0 + qb + g + 8) * D_MODEL + h * DK;
#pragma unroll
    for (int nt = 0; nt < 8; nt++) {
        int d = 8 * nt + 2 * tg;
        float2 o0, o1;
        if (qok0) { o0.x = of[nt][0] * inv0; o0.y = of[nt][1] * inv0; }
        else      { o0.x = s.vred[d] * u;    o0.y = s.vred[d + 1] * u; }
        if (qok1) { o1.x = of[nt][2] * inv1; o1.y = of[nt][3] * inv1; }
        else      { o1.x = s.vred[d] * u;    o1.y = s.vred[d + 1] * u; }
        *(float2*)&op0[d] = o0;
        *(float2*)&op1[d] = o1;
    }
}

// ----------------------------------------------------------------------------
// Inputs (metadata order): x, K, V, Wq, Wo, kv_pad_mask, q_pad_mask
// ----------------------------------------------------------------------------
extern "C" void kernel_launch(void* const* d_in, const int* in_sizes, int n_in,
                              void* d_out, int out_size)
{
    const float*    x   = (const float*)d_in[0];
    const float*    K   = (const float*)d_in[1];
    const float*    V   = (const float*)d_in[2];
    const float*    Wq  = (const float*)d_in[3];
    const float*    Wo  = (const float*)d_in[4];
    const unsigned* kvm = (const unsigned*)d_in[5];
    const unsigned* qm  = (const unsigned*)d_in[6];
    float*          out = (float*)d_out;

    float *gQ, *gA;
    cudaGetSymbolAddress((void**)&gQ, g_Q);
    cudaGetSymbolAddress((void**)&gA, g_attn);

    const int M = BATCH * NQ;
    dim3 gemm_grid(D_MODEL / 128, M / 128);

    const int ATTN_SMEM = (int)sizeof(AttnSmem);
    cudaFuncSetAttribute(attn_mma, cudaFuncAttributeMaxDynamicSharedMemorySize, ATTN_SMEM);

    gemm_tc<<<gemm_grid, 256>>>(x, Wq, gQ, M, D_MODEL, D_MODEL);

    dim3 attn_grid(NQ / 128, NHEAD, BATCH);
    attn_mma<<<attn_grid, 256, ATTN_SMEM>>>(gQ, K, V, kvm, qm, gA);

    gemm_tc<<<gemm_grid, 256>>>(gA, Wo, out, M, D_MODEL, D_MODEL);
}

// round 14
// speedup vs baseline: 1.1656x; 1.1656x over previous
#include <cuda_runtime.h>
#include <cstdint>
#include <math.h>

#define D_MODEL 1024
#define NHEAD   16
#define DK      64
#define BATCH   2
#define NQ      2048
#define NKV     2048

// Scratch (allocation-free)
__device__ float g_Q[BATCH * NQ * D_MODEL];
__device__ float g_attn[BATCH * NQ * D_MODEL];

__device__ __forceinline__ float to_tf32(float x) {
    float r; asm("cvt.rna.tf32.f32 %0, %1;" : "=f"(r) : "f"(x));
    return r;
}
__device__ __forceinline__ uint32_t tf32u(float x) {
    return __float_as_uint(to_tf32(x));
}
__device__ __forceinline__ float ex2f(float x) {
    float r; asm("ex2.approx.f32 %0, %1;" : "=f"(r) : "f"(x)); return r;
}

// m16n8k8 tf32 mma (sm_80+ path; compiles for plain sm_103)
__device__ __forceinline__ void mma_tf32(float* c, const uint32_t* a,
                                         uint32_t b0, uint32_t b1) {
    asm volatile(
        "mma.sync.aligned.m16n8k8.row.col.f32.tf32.tf32.f32 "
        "{%0,%1,%2,%3},{%4,%5,%6,%7},{%8,%9},{%0,%1,%2,%3};"
        : "+f"(c[0]), "+f"(c[1]), "+f"(c[2]), "+f"(c[3])
        : "r"(a[0]), "r"(a[1]), "r"(a[2]), "r"(a[3]), "r"(b0), "r"(b1));
}

// ----------------------------------------------------------------------------
// Tensor-core GEMM, tf32x1, warp tile 64x64 (mt=4, nt=8): LDS/mma = 1.0.
// Block 128 threads (4 warps, 2x2), block tile 128x128, K-chunk 16.
// R12 skeleton: register prefetch, single-buffered smem, convert at staging.
// Strides: A 20 (banks 20g+tg), B 136 (banks 8tg+g) -> conflict-free.
// ----------------------------------------------------------------------------
__global__ __launch_bounds__(128, 2) void gemm_tc(const float* __restrict__ A,
                                                  const float* __restrict__ B,
                                                  float* __restrict__ C,
                                                  int M, int N, int K)
{
    __shared__ float Ash[128][20];   // A (tf32)
    __shared__ float Bsh[16][136];   // B (tf32)

    const int tid  = threadIdx.x;
    const int warp = tid >> 5;
    const int lane = tid & 31;
    const int g    = lane >> 2;
    const int tg   = lane & 3;
    const int wm   = (warp & 1) * 64;      // 2 warps in M
    const int wn   = (warp >> 1) * 64;     // 2 warps in N
    const int cRow = blockIdx.y * 128;
    const int cCol = blockIdx.x * 128;

    // staging indices (128 threads)
    const int ar  = tid >> 2;         // A rows ar + {0,32,64,96}
    const int ac4 = (tid & 3) * 4;    // A col group
    const int br  = tid >> 5;         // B rows br + {0,4,8,12}
    const int bc4 = (tid & 31) * 4;   // B col group

    float cacc[4][8][4];
#pragma unroll
    for (int mt = 0; mt < 4; mt++)
#pragma unroll
        for (int nt = 0; nt < 8; nt++)
#pragma unroll
            for (int j = 0; j < 4; j++) cacc[mt][nt][j] = 0.f;

    // prefetch chunk 0
    float4 pa[4], pb[4];
#pragma unroll
    for (int i = 0; i < 4; i++) {
        pa[i] = *(const float4*)&A[(size_t)(cRow + ar + i * 32) * K + ac4];
        pb[i] = *(const float4*)&B[(size_t)(br + i * 4) * N + cCol + bc4];
    }

    const int NC = K / 16;
    for (int kc = 0; kc < NC; kc++) {
        // ---- stage (tf32 truncate once) ----
        {
            float4 hv;
#define CVT4(src, dsth) \
            hv.x = to_tf32(src.x); hv.y = to_tf32(src.y); \
            hv.z = to_tf32(src.z); hv.w = to_tf32(src.w); \
            *(float4*)&dsth = hv;
#pragma unroll
            for (int i = 0; i < 4; i++) {
                CVT4(pa[i], Ash[ar + i * 32][ac4]);
                CVT4(pb[i], Bsh[br + i * 4][bc4]);
            }
#undef CVT4
        }
        __syncthreads();

        // prefetch next chunk while mma runs
        if (kc + 1 < NC) {
            int k0 = (kc + 1) * 16;
#pragma unroll
            for (int i = 0; i < 4; i++) {
                pa[i] = *(const float4*)&A[(size_t)(cRow + ar + i * 32) * K + k0 + ac4];
                pb[i] = *(const float4*)&B[(size_t)(k0 + br + i * 4) * N + cCol + bc4];
            }
        }

        // ---- mma over 2 k-steps of 8 ----
#pragma unroll
        for (int ks = 0; ks < 2; ks++) {
            const int k8 = ks * 8;
            uint32_t ah[4][4];
#pragma unroll
            for (int mt = 0; mt < 4; mt++) {
                int m0 = wm + mt * 16 + g;
                ah[mt][0] = __float_as_uint(Ash[m0][k8 + tg]);
                ah[mt][1] = __float_as_uint(Ash[m0 + 8][k8 + tg]);
                ah[mt][2] = __float_as_uint(Ash[m0][k8 + tg + 4]);
                ah[mt][3] = __float_as_uint(Ash[m0 + 8][k8 + tg + 4]);
            }
#pragma unroll
            for (int nt = 0; nt < 8; nt++) {
                int n0 = wn + nt * 8 + g;
                uint32_t bh0 = __float_as_uint(Bsh[k8 + tg][n0]);
                uint32_t bh1 = __float_as_uint(Bsh[k8 + tg + 4][n0]);
#pragma unroll
                for (int mt = 0; mt < 4; mt++)
                    mma_tf32(cacc[mt][nt], ah[mt], bh0, bh1);
            }
        }
        __syncthreads();
    }

#pragma unroll
    for (int mt = 0; mt < 4; mt++) {
        int row0 = cRow + wm + mt * 16 + g;
#pragma unroll
        for (int nt = 0; nt < 8; nt++) {
            int col = cCol + wn + nt * 8 + 2 * tg;
            *(float2*)&C[(size_t)row0 * N + col]       = make_float2(cacc[mt][nt][0], cacc[mt][nt][1]);
            *(float2*)&C[(size_t)(row0 + 8) * N + col] = make_float2(cacc[mt][nt][2], cacc[mt][nt][3]);
        }
    }
}

// ----------------------------------------------------------------------------
// Tensor-core attention via mma.sync tf32 (exp-without-max). Exact R12 version.
// ----------------------------------------------------------------------------
struct AttnSmem {
    uint32_t Ks[64][68];
    uint32_t Vs[64][72];
    uint32_t Ps[128][68];
    float    kvsel[64];
    float    vred[64];
};

__global__ __launch_bounds__(256, 2) void attn_mma(
    const float* __restrict__ Q,
    const float* __restrict__ Kin,
    const float* __restrict__ Vin,
    const unsigned* __restrict__ kvmask,
    const unsigned* __restrict__ qmask,
    float* __restrict__ attn)
{
    extern __shared__ AttnSmem smem_raw[];
    AttnSmem& s = smem_raw[0];

    const int tid  = threadIdx.x;
    const int warp = tid >> 5;
    const int lane = tid & 31;
    const int g    = lane >> 2;
    const int tg   = lane & 3;
    const int b    = blockIdx.z;
    const int h    = blockIdx.y;
    const int q0   = blockIdx.x * 128;
    const int qb   = warp * 16;
    const float C2 = 0.18033688011112042f;   // 0.125 * log2(e)

    uint32_t qf[8][4];
    {
        const float* qp = Q + (size_t)(b * NQ + q0 + qb) * D_MODEL + h * DK;
#pragma unroll
        for (int ks = 0; ks < 8; ks++) {
            qf[ks][0] = tf32u(qp[(size_t)g       * D_MODEL + 8 * ks + tg]);
            qf[ks][1] = tf32u(qp[(size_t)(g + 8) * D_MODEL + 8 * ks + tg]);
            qf[ks][2] = tf32u(qp[(size_t)g       * D_MODEL + 8 * ks + tg + 4]);
            qf[ks][3] = tf32u(qp[(size_t)(g + 8) * D_MODEL + 8 * ks + tg + 4]);
        }
    }

    float of[8][4];
#pragma unroll
    for (int nt = 0; nt < 8; nt++)
#pragma unroll
        for (int j = 0; j < 4; j++) of[nt][j] = 0.f;
    float l0 = 0.f, l1 = 0.f;
    float4 vsum = make_float4(0.f, 0.f, 0.f, 0.f);

    if (tid < 64) s.vred[tid] = 0.f;

    const float* Kb = Kin + (size_t)(b * NHEAD + h) * NKV * DK;
    const float* Vb = Vin + (size_t)(b * NHEAD + h) * NKV * DK;
    const int c4 = (tid & 15) * 4;
    const int r0 = tid >> 4;

    for (int t = 0; t < NKV / 64; t++) {
        const int k0 = t * 64;
        __syncthreads();

#pragma unroll
        for (int i = 0; i < 4; i++) {
            int r = r0 + i * 16;
            float4 k4 = *(const float4*)&Kb[(size_t)(k0 + r) * DK + c4];
            uint4 ku = make_uint4(tf32u(k4.x), tf32u(k4.y), tf32u(k4.z), tf32u(k4.w));
            *(uint4*)&s.Ks[r][c4] = ku;
            float4 v4 = *(const float4*)&Vb[(size_t)(k0 + r) * DK + c4];
            vsum.x += v4.x; vsum.y += v4.y; vsum.z += v4.z; vsum.w += v4.w;
            uint4 vu = make_uint4(tf32u(v4.x), tf32u(v4.y), tf32u(v4.z), tf32u(v4.w));
            *(uint4*)&s.Vs[r][c4] = vu;
        }
        if (tid < 64)
            s.kvsel[tid] = (kvmask[b * NKV + k0 + tid] != 0u) ? 0.f : -1e9f;
        __syncthreads();

        float sc[8][4];
#pragma unroll
        for (int nt = 0; nt < 8; nt++)
#pragma unroll
            for (int j = 0; j < 4; j++) sc[nt][j] = 0.f;
#pragma unroll
        for (int ks = 0; ks < 8; ks++) {
#pragma unroll
            for (int nt = 0; nt < 8; nt++) {
                uint32_t kb0 = s.Ks[8 * nt + g][8 * ks + tg];
                uint32_t kb1 = s.Ks[8 * nt + g][8 * ks + tg + 4];
                mma_tf32(sc[nt], qf[ks], kb0, kb1);
            }
        }

        // ---- epilogue: p = 2^(s*C2 + sel), accumulate l, store P (tf32) ----
#pragma unroll
        for (int nt = 0; nt < 8; nt++) {
            float s0 = s.kvsel[8 * nt + 2 * tg];
            float s1 = s.kvsel[8 * nt + 2 * tg + 1];
            float p0 = ex2f(fmaf(sc[nt][0], C2, s0));
            float p1 = ex2f(fmaf(sc[nt][1], C2, s1));
            float p2 = ex2f(fmaf(sc[nt][2], C2, s0));
            float p3 = ex2f(fmaf(sc[nt][3], C2, s1));
            l0 += p0 + p1;
            l1 += p2 + p3;
            uint2 w0 = make_uint2(tf32u(p0), tf32u(p1));
            uint2 w1 = make_uint2(tf32u(p2), tf32u(p3));
            *(uint2*)&s.Ps[qb + g][8 * nt + 2 * tg]     = w0;
            *(uint2*)&s.Ps[qb + g + 8][8 * nt + 2 * tg] = w1;
        }
        __syncwarp();   // Ps is warp-private

#pragma unroll
        for (int ks = 0; ks < 8; ks++) {
            uint32_t pa[4];
            pa[0] = s.Ps[qb + g][8 * ks + tg];
            pa[1] = s.Ps[qb + g + 8][8 * ks + tg];
            pa[2] = s.Ps[qb + g][8 * ks + tg + 4];
            pa[3] = s.Ps[qb + g + 8][8 * ks + tg + 4];
#pragma unroll
            for (int nt = 0; nt < 8; nt++) {
                uint32_t vb0 = s.Vs[8 * ks + tg][8 * nt + g];
                uint32_t vb1 = s.Vs[8 * ks + tg + 4][8 * nt + g];
                mma_tf32(of[nt], pa, vb0, vb1);
            }
        }
    }

    atomicAdd(&s.vred[c4 + 0], vsum.x);
    atomicAdd(&s.vred[c4 + 1], vsum.y);
    atomicAdd(&s.vred[c4 + 2], vsum.z);
    atomicAdd(&s.vred[c4 + 3], vsum.w);
    __syncthreads();

    l0 += __shfl_xor_sync(0xffffffffu, l0, 1);
    l0 += __shfl_xor_sync(0xffffffffu, l0, 2);
    l1 += __shfl_xor_sync(0xffffffffu, l1, 1);
    l1 += __shfl_xor_sync(0xffffffffu, l1, 2);
    const float inv0 = 1.f / l0;
    const float inv1 = 1.f / l1;
    const bool qok0 = (qmask[b * NQ + q0 + qb + g]     != 0u);
    const bool qok1 = (qmask[b * NQ + q0 + qb + g + 8] != 0u);
    const float u = 1.f / 2048.f;

    float* op0 = attn + (size_t)(b * NQ + q0 + qb + g)     * D_MODEL + h * DK;
    float* op1 = attn + (size_t)(b * NQ + q0 + qb + g + 8) * D_MODEL + h * DK;
#pragma unroll
    for (int nt = 0; nt < 8; nt++) {
        int d = 8 * nt + 2 * tg;
        float2 o0, o1;
        if (qok0) { o0.x = of[nt][0] * inv0; o0.y = of[nt][1] * inv0; }
        else      { o0.x = s.vred[d] * u;    o0.y = s.vred[d + 1] * u; }
        if (qok1) { o1.x = of[nt][2] * inv1; o1.y = of[nt][3] * inv1; }
        else      { o1.x = s.vred[d] * u;    o1.y = s.vred[d + 1] * u; }
        *(float2*)&op0[d] = o0;
        *(float2*)&op1[d] = o1;
    }
}

// ----------------------------------------------------------------------------
// Inputs (metadata order): x, K, V, Wq, Wo, kv_pad_mask, q_pad_mask
// ----------------------------------------------------------------------------
extern "C" void kernel_launch(void* const* d_in, const int* in_sizes, int n_in,
                              void* d_out, int out_size)
{
    const float*    x   = (const float*)d_in[0];
    const float*    K   = (const float*)d_in[1];
    const float*    V   = (const float*)d_in[2];
    const float*    Wq  = (const float*)d_in[3];
    const float*    Wo  = (const float*)d_in[4];
    const unsigned* kvm = (const unsigned*)d_in[5];
    const unsigned* qm  = (const unsigned*)d_in[6];
    float*          out = (float*)d_out;

    float *gQ, *gA;
    cudaGetSymbolAddress((void**)&gQ, g_Q);
    cudaGetSymbolAddress((void**)&gA, g_attn);

    const int M = BATCH * NQ;
    dim3 gemm_grid(D_MODEL / 128, M / 128);

    const int ATTN_SMEM = (int)sizeof(AttnSmem);
    cudaFuncSetAttribute(attn_mma, cudaFuncAttributeMaxDynamicSharedMemorySize, ATTN_SMEM);

    gemm_tc<<<gemm_grid, 128>>>(x, Wq, gQ, M, D_MODEL, D_MODEL);

    dim3 attn_grid(NQ / 128, NHEAD, BATCH);
    attn_mma<<<attn_grid, 256, ATTN_SMEM>>>(gQ, K, V, kvm, qm, gA);

    gemm_tc<<<gemm_grid, 128>>>(gA, Wo, out, M, D_MODEL, D_MODEL);
}

// round 15
// speedup vs baseline: 1.3220x; 1.1342x over previous
#include <cuda_runtime.h>
#include <cstdint>
#include <math.h>

#define D_MODEL 1024
#define NHEAD   16
#define DK      64
#define BATCH   2
#define NQ      2048
#define NKV     2048

// Scratch (allocation-free)
__device__ float g_Q[BATCH * NQ * D_MODEL];
__device__ float g_attn[BATCH * NQ * D_MODEL];

__device__ __forceinline__ float to_tf32(float x) {
    float r; asm("cvt.rna.tf32.f32 %0, %1;" : "=f"(r) : "f"(x));
    return r;
}
__device__ __forceinline__ uint32_t tf32u(float x) {
    return __float_as_uint(to_tf32(x));
}
__device__ __forceinline__ float ex2f(float x) {
    float r; asm("ex2.approx.f32 %0, %1;" : "=f"(r) : "f"(x)); return r;
}

// m16n8k8 tf32 mma (sm_80+ path; compiles for plain sm_103)
__device__ __forceinline__ void mma_tf32(float* c, const uint32_t* a,
                                         uint32_t b0, uint32_t b1) {
    asm volatile(
        "mma.sync.aligned.m16n8k8.row.col.f32.tf32.tf32.f32 "
        "{%0,%1,%2,%3},{%4,%5,%6,%7},{%8,%9},{%0,%1,%2,%3};"
        : "+f"(c[0]), "+f"(c[1]), "+f"(c[2]), "+f"(c[3])
        : "r"(a[0]), "r"(a[1]), "r"(a[2]), "r"(a[3]), "r"(b0), "r"(b1));
}

// ----------------------------------------------------------------------------
// Tensor-core GEMM, tf32x1, warp tile 64x64 (mt=4, nt=8): LDS/mma = 1.0.
// Block 128 threads (4 warps, 2x2), block tile 128x128, K-chunk 16.
// (Unchanged from R14: 71 us.)
// ----------------------------------------------------------------------------
__global__ __launch_bounds__(128, 2) void gemm_tc(const float* __restrict__ A,
                                                  const float* __restrict__ B,
                                                  float* __restrict__ C,
                                                  int M, int N, int K)
{
    __shared__ float Ash[128][20];   // A (tf32)
    __shared__ float Bsh[16][136];   // B (tf32)

    const int tid  = threadIdx.x;
    const int warp = tid >> 5;
    const int lane = tid & 31;
    const int g    = lane >> 2;
    const int tg   = lane & 3;
    const int wm   = (warp & 1) * 64;      // 2 warps in M
    const int wn   = (warp >> 1) * 64;     // 2 warps in N
    const int cRow = blockIdx.y * 128;
    const int cCol = blockIdx.x * 128;

    const int ar  = tid >> 2;         // A rows ar + {0,32,64,96}
    const int ac4 = (tid & 3) * 4;    // A col group
    const int br  = tid >> 5;         // B rows br + {0,4,8,12}
    const int bc4 = (tid & 31) * 4;   // B col group

    float cacc[4][8][4];
#pragma unroll
    for (int mt = 0; mt < 4; mt++)
#pragma unroll
        for (int nt = 0; nt < 8; nt++)
#pragma unroll
            for (int j = 0; j < 4; j++) cacc[mt][nt][j] = 0.f;

    float4 pa[4], pb[4];
#pragma unroll
    for (int i = 0; i < 4; i++) {
        pa[i] = *(const float4*)&A[(size_t)(cRow + ar + i * 32) * K + ac4];
        pb[i] = *(const float4*)&B[(size_t)(br + i * 4) * N + cCol + bc4];
    }

    const int NC = K / 16;
    for (int kc = 0; kc < NC; kc++) {
        {
            float4 hv;
#define CVT4(src, dsth) \
            hv.x = to_tf32(src.x); hv.y = to_tf32(src.y); \
            hv.z = to_tf32(src.z); hv.w = to_tf32(src.w); \
            *(float4*)&dsth = hv;
#pragma unroll
            for (int i = 0; i < 4; i++) {
                CVT4(pa[i], Ash[ar + i * 32][ac4]);
                CVT4(pb[i], Bsh[br + i * 4][bc4]);
            }
#undef CVT4
        }
        __syncthreads();

        if (kc + 1 < NC) {
            int k0 = (kc + 1) * 16;
#pragma unroll
            for (int i = 0; i < 4; i++) {
                pa[i] = *(const float4*)&A[(size_t)(cRow + ar + i * 32) * K + k0 + ac4];
                pb[i] = *(const float4*)&B[(size_t)(k0 + br + i * 4) * N + cCol + bc4];
            }
        }

#pragma unroll
        for (int ks = 0; ks < 2; ks++) {
            const int k8 = ks * 8;
            uint32_t ah[4][4];
#pragma unroll
            for (int mt = 0; mt < 4; mt++) {
                int m0 = wm + mt * 16 + g;
                ah[mt][0] = __float_as_uint(Ash[m0][k8 + tg]);
                ah[mt][1] = __float_as_uint(Ash[m0 + 8][k8 + tg]);
                ah[mt][2] = __float_as_uint(Ash[m0][k8 + tg + 4]);
                ah[mt][3] = __float_as_uint(Ash[m0 + 8][k8 + tg + 4]);
            }
#pragma unroll
            for (int nt = 0; nt < 8; nt++) {
                int n0 = wn + nt * 8 + g;
                uint32_t bh0 = __float_as_uint(Bsh[k8 + tg][n0]);
                uint32_t bh1 = __float_as_uint(Bsh[k8 + tg + 4][n0]);
#pragma unroll
                for (int mt = 0; mt < 4; mt++)
                    mma_tf32(cacc[mt][nt], ah[mt], bh0, bh1);
            }
        }
        __syncthreads();
    }

#pragma unroll
    for (int mt = 0; mt < 4; mt++) {
        int row0 = cRow + wm + mt * 16 + g;
#pragma unroll
        for (int nt = 0; nt < 8; nt++) {
            int col = cCol + wn + nt * 8 + 2 * tg;
            *(float2*)&C[(size_t)row0 * N + col]       = make_float2(cacc[mt][nt][0], cacc[mt][nt][1]);
            *(float2*)&C[(size_t)(row0 + 8) * N + col] = make_float2(cacc[mt][nt][2], cacc[mt][nt][3]);
        }
    }
}

// ----------------------------------------------------------------------------
// Tensor-core attention (tf32 mma, exp-without-max), warp tile 32q x 64kv
// (mt=2): LDS/mma = 1.25 (was 2.25). Block 128 threads (4 warps), q-tile 128,
// kv-tile 64. Strides: Ks/Ps 68 (banks 4g+tg), Vs 72 (banks 8tg+g).
// ----------------------------------------------------------------------------
struct AttnSmem {
    uint32_t Ks[64][68];
    uint32_t Vs[64][72];
    uint32_t Ps[128][68];
    float    kvsel[64];
    float    vred[64];
};

__global__ __launch_bounds__(128, 2) void attn_mma(
    const float* __restrict__ Q,
    const float* __restrict__ Kin,
    const float* __restrict__ Vin,
    const unsigned* __restrict__ kvmask,
    const unsigned* __restrict__ qmask,
    float* __restrict__ attn)
{
    extern __shared__ AttnSmem smem_raw[];
    AttnSmem& s = smem_raw[0];

    const int tid  = threadIdx.x;
    const int warp = tid >> 5;
    const int lane = tid & 31;
    const int g    = lane >> 2;
    const int tg   = lane & 3;
    const int b    = blockIdx.z;
    const int h    = blockIdx.y;
    const int q0   = blockIdx.x * 128;
    const int qb   = warp * 32;          // 32 q rows per warp
    const float C2 = 0.18033688011112042f;   // 0.125 * log2(e)

    // ---- Q fragments for 2 m-tiles, resident in regs ----
    uint32_t qf[2][8][4];
    {
        const float* qp = Q + (size_t)(b * NQ + q0 + qb) * D_MODEL + h * DK;
#pragma unroll
        for (int mt = 0; mt < 2; mt++)
#pragma unroll
            for (int ks = 0; ks < 8; ks++) {
                qf[mt][ks][0] = tf32u(qp[(size_t)(mt * 16 + g)     * D_MODEL + 8 * ks + tg]);
                qf[mt][ks][1] = tf32u(qp[(size_t)(mt * 16 + g + 8) * D_MODEL + 8 * ks + tg]);
                qf[mt][ks][2] = tf32u(qp[(size_t)(mt * 16 + g)     * D_MODEL + 8 * ks + tg + 4]);
                qf[mt][ks][3] = tf32u(qp[(size_t)(mt * 16 + g + 8) * D_MODEL + 8 * ks + tg + 4]);
            }
    }

    float of[2][8][4];
#pragma unroll
    for (int mt = 0; mt < 2; mt++)
#pragma unroll
        for (int nt = 0; nt < 8; nt++)
#pragma unroll
            for (int j = 0; j < 4; j++) of[mt][nt][j] = 0.f;
    float lr[2][2] = {{0.f, 0.f}, {0.f, 0.f}};   // [mt][row-half]
    float4 vsum = make_float4(0.f, 0.f, 0.f, 0.f);

    if (tid < 64) s.vred[tid] = 0.f;

    const float* Kb = Kin + (size_t)(b * NHEAD + h) * NKV * DK;
    const float* Vb = Vin + (size_t)(b * NHEAD + h) * NKV * DK;
    const int c4 = (tid & 15) * 4;   // dk col group (staging)
    const int r0 = tid >> 4;         // base kv row 0..7 (staging)

    for (int t = 0; t < NKV / 64; t++) {
        const int k0 = t * 64;
        __syncthreads();

        // ---- stage K/V tile (tf32), 8 rows per pass ----
#pragma unroll
        for (int i = 0; i < 8; i++) {
            int r = r0 + i * 8;
            float4 k4 = *(const float4*)&Kb[(size_t)(k0 + r) * DK + c4];
            uint4 ku = make_uint4(tf32u(k4.x), tf32u(k4.y), tf32u(k4.z), tf32u(k4.w));
            *(uint4*)&s.Ks[r][c4] = ku;
            float4 v4 = *(const float4*)&Vb[(size_t)(k0 + r) * DK + c4];
            vsum.x += v4.x; vsum.y += v4.y; vsum.z += v4.z; vsum.w += v4.w;
            uint4 vu = make_uint4(tf32u(v4.x), tf32u(v4.y), tf32u(v4.z), tf32u(v4.w));
            *(uint4*)&s.Vs[r][c4] = vu;
        }
        if (tid < 64)
            s.kvsel[tid] = (kvmask[b * NKV + k0 + tid] != 0u) ? 0.f : -1e9f;
        __syncthreads();

        // ---- S = Q K^T (K fragments amortized over 2 m-tiles) ----
        float sc[2][8][4];
#pragma unroll
        for (int mt = 0; mt < 2; mt++)
#pragma unroll
            for (int nt = 0; nt < 8; nt++)
#pragma unroll
                for (int j = 0; j < 4; j++) sc[mt][nt][j] = 0.f;
#pragma unroll
        for (int ks = 0; ks < 8; ks++) {
#pragma unroll
            for (int nt = 0; nt < 8; nt++) {
                uint32_t kb0 = s.Ks[8 * nt + g][8 * ks + tg];
                uint32_t kb1 = s.Ks[8 * nt + g][8 * ks + tg + 4];
                mma_tf32(sc[0][nt], qf[0][ks], kb0, kb1);
                mma_tf32(sc[1][nt], qf[1][ks], kb0, kb1);
            }
        }

        // ---- epilogue: p = 2^(s*C2 + sel), accumulate l, store P (tf32) ----
#pragma unroll
        for (int nt = 0; nt < 8; nt++) {
            float s0 = s.kvsel[8 * nt + 2 * tg];
            float s1 = s.kvsel[8 * nt + 2 * tg + 1];
#pragma unroll
            for (int mt = 0; mt < 2; mt++) {
                float p0 = ex2f(fmaf(sc[mt][nt][0], C2, s0));
                float p1 = ex2f(fmaf(sc[mt][nt][1], C2, s1));
                float p2 = ex2f(fmaf(sc[mt][nt][2], C2, s0));
                float p3 = ex2f(fmaf(sc[mt][nt][3], C2, s1));
                lr[mt][0] += p0 + p1;
                lr[mt][1] += p2 + p3;
                uint2 w0 = make_uint2(tf32u(p0), tf32u(p1));
                uint2 w1 = make_uint2(tf32u(p2), tf32u(p3));
                *(uint2*)&s.Ps[qb + mt * 16 + g][8 * nt + 2 * tg]     = w0;
                *(uint2*)&s.Ps[qb + mt * 16 + g + 8][8 * nt + 2 * tg] = w1;
            }
        }
        __syncwarp();   // Ps is warp-private

        // ---- O += P V (V fragments amortized over 2 m-tiles) ----
#pragma unroll
        for (int ks = 0; ks < 8; ks++) {
            uint32_t pa[2][4];
#pragma unroll
            for (int mt = 0; mt < 2; mt++) {
                pa[mt][0] = s.Ps[qb + mt * 16 + g][8 * ks + tg];
                pa[mt][1] = s.Ps[qb + mt * 16 + g + 8][8 * ks + tg];
                pa[mt][2] = s.Ps[qb + mt * 16 + g][8 * ks + tg + 4];
                pa[mt][3] = s.Ps[qb + mt * 16 + g + 8][8 * ks + tg + 4];
            }
#pragma unroll
            for (int nt = 0; nt < 8; nt++) {
                uint32_t vb0 = s.Vs[8 * ks + tg][8 * nt + g];
                uint32_t vb1 = s.Vs[8 * ks + tg + 4][8 * nt + g];
                mma_tf32(of[0][nt], pa[0], vb0, vb1);
                mma_tf32(of[1][nt], pa[1], vb0, vb1);
            }
        }
    }

    // ---- mean(V) reduction for masked q rows ----
    atomicAdd(&s.vred[c4 + 0], vsum.x);
    atomicAdd(&s.vred[c4 + 1], vsum.y);
    atomicAdd(&s.vred[c4 + 2], vsum.z);
    atomicAdd(&s.vred[c4 + 3], vsum.w);
    __syncthreads();

    // ---- l reduction across quad lanes; output ----
#pragma unroll
    for (int mt = 0; mt < 2; mt++) {
#pragma unroll
        for (int hf = 0; hf < 2; hf++) {
            lr[mt][hf] += __shfl_xor_sync(0xffffffffu, lr[mt][hf], 1);
            lr[mt][hf] += __shfl_xor_sync(0xffffffffu, lr[mt][hf], 2);
        }
    }
    const float u = 1.f / 2048.f;
#pragma unroll
    for (int mt = 0; mt < 2; mt++) {
        const float inv0 = 1.f / lr[mt][0];
        const float inv1 = 1.f / lr[mt][1];
        const bool qok0 = (qmask[b * NQ + q0 + qb + mt * 16 + g]     != 0u);
        const bool qok1 = (qmask[b * NQ + q0 + qb + mt * 16 + g + 8] != 0u);
        float* op0 = attn + (size_t)(b * NQ + q0 + qb + mt * 16 + g)     * D_MODEL + h * DK;
        float* op1 = attn + (size_t)(b * NQ + q0 + qb + mt * 16 + g + 8) * D_MODEL + h * DK;
#pragma unroll
        for (int nt = 0; nt < 8; nt++) {
            int d = 8 * nt + 2 * tg;
            float2 o0, o1;
            if (qok0) { o0.x = of[mt][nt][0] * inv0; o0.y = of[mt][nt][1] * inv0; }
            else      { o0.x = s.vred[d] * u;        o0.y = s.vred[d + 1] * u; }
            if (qok1) { o1.x = of[mt][nt][2] * inv1; o1.y = of[mt][nt][3] * inv1; }
            else      { o1.x = s.vred[d] * u;        o1.y = s.vred[d + 1] * u; }
            *(float2*)&op0[d] = o0;
            *(float2*)&op1[d] = o1;
        }
    }
}

// ----------------------------------------------------------------------------
// Inputs (metadata order): x, K, V, Wq, Wo, kv_pad_mask, q_pad_mask
// ----------------------------------------------------------------------------
extern "C" void kernel_launch(void* const* d_in, const int* in_sizes, int n_in,
                              void* d_out, int out_size)
{
    const float*    x   = (const float*)d_in[0];
    const float*    K   = (const float*)d_in[1];
    const float*    V   = (const float*)d_in[2];
    const float*    Wq  = (const float*)d_in[3];
    const float*    Wo  = (const float*)d_in[4];
    const unsigned* kvm = (const unsigned*)d_in[5];
    const unsigned* qm  = (const unsigned*)d_in[6];
    float*          out = (float*)d_out;

    float *gQ, *gA;
    cudaGetSymbolAddress((void**)&gQ, g_Q);
    cudaGetSymbolAddress((void**)&gA, g_attn);

    const int M = BATCH * NQ;
    dim3 gemm_grid(D_MODEL / 128, M / 128);

    const int ATTN_SMEM = (int)sizeof(AttnSmem);
    cudaFuncSetAttribute(attn_mma, cudaFuncAttributeMaxDynamicSharedMemorySize, ATTN_SMEM);

    gemm_tc<<<gemm_grid, 128>>>(x, Wq, gQ, M, D_MODEL, D_MODEL);

    dim3 attn_grid(NQ / 128, NHEAD, BATCH);
    attn_mma<<<attn_grid, 128, ATTN_SMEM>>>(gQ, K, V, kvm, qm, gA);

    gemm_tc<<<gemm_grid, 128>>>(gA, Wo, out, M, D_MODEL, D_MODEL);
}